// round 11
// baseline (speedup 1.0000x reference)
#include <cuda_runtime.h>
#include <math.h>

#define B_SETS 65536
#define P      22
#define INF_   6
#define HID    64
#define OUTD   128

#define WPB     8
#define THREADS (WPB * 32)
#define GRID    592                 // 148 SMs * 4 blocks/SM
#define S       4
#define NCHUNKS (B_SETS / S)        // 16384
#define NWARPS  (GRID * WPB)        // 4736
#define BASE_CHUNKS (NWARPS * 3)    // 14208 ; tail = 2176 = NWARPS*17/37

__device__ __forceinline__ unsigned long long pack2(float lo, float hi) {
    unsigned long long r;
    asm("mov.b64 %0, {%1,%2};" : "=l"(r) : "f"(lo), "f"(hi));
    return r;
}
__device__ __forceinline__ void unpack2(unsigned long long v, float& lo, float& hi) {
    asm("mov.b64 {%0,%1}, %2;" : "=f"(lo), "=f"(hi) : "l"(v));
}
__device__ __forceinline__ unsigned long long fma2(unsigned long long a,
                                                   unsigned long long b,
                                                   unsigned long long c) {
    unsigned long long d;
    asm("fma.rn.f32x2 %0, %1, %2, %3;" : "=l"(d) : "l"(a), "l"(b), "l"(c));
    return d;
}

// fast atan2: minimax deg-11 odd poly on [0,1], abs err ~1e-6 (output tol 1e-3)
__device__ __forceinline__ float fast_atan2(float y, float x) {
    const float ax = fabsf(x), ay = fabsf(y);
    const float mx = fmaxf(ax, ay), mn = fminf(ax, ay);
    float t = (mx > 0.f) ? __fdividef(mn, mx) : 0.f;
    const float a = t * t;
    float p = fmaf(a, -0.01172120f, 0.05265332f);
    p = fmaf(a, p, -0.11643287f);
    p = fmaf(a, p,  0.19354346f);
    p = fmaf(a, p, -0.33262347f);
    p = fmaf(a, p,  0.99997726f);
    float r = t * p;
    if (ay > ax)  r = 1.57079632679f - r;
    if (x < 0.f)  r = 3.14159265359f - r;
    return (y < 0.f) ? -r : r;
}

__global__ __launch_bounds__(THREADS, 4)
void set_encoder_kernel(const float* __restrict__ player_locs,
                        const float* __restrict__ actor_locs,
                        const float* __restrict__ flags,
                        const int*   __restrict__ mask,
                        const float* __restrict__ W1,
                        const float* __restrict__ b1,
                        const float* __restrict__ W2,
                        const float* __restrict__ b2,
                        float*       __restrict__ out)
{
    __shared__ float  sW2[HID * OUTD];            // 32 KB
    __shared__ float  shh[WPB][HID][S];           // pooled hidden per warp
    __shared__ float4 sfd[WPB][P][3];             // duplicated features:
                                                  // (dx,dx,dy,dy)(dist,dist,ang,ang)(tm,tm,kp,kp)

    const int tid  = threadIdx.x;
    const int lane = tid & 31;
    const int wip  = tid >> 5;

    {   // stage W2 into shared once per block
        const float4* W2v  = (const float4*)W2;
        float4*       sW2v = (float4*)sW2;
        #pragma unroll
        for (int i = tid; i < HID * OUTD / 4; i += THREADS) sW2v[i] = W2v[i];
    }

    // W1 column pair (lane, lane+32) packed for f32x2
    unsigned long long w1ab[INF_];
    #pragma unroll
    for (int i = 0; i < INF_; i++)
        w1ab[i] = pack2(W1[i * HID + lane], W1[i * HID + lane + 32]);
    const unsigned long long b1ab = pack2(b1[lane], b1[lane + 32]);
    float bv[4];
    {   const float4 t = ((const float4*)b2)[lane];
        bv[0] = t.x; bv[1] = t.y; bv[2] = t.z; bv[3] = t.w; }

    __syncthreads();

    const int w = blockIdx.x * WPB + wip;   // global warp id

    // Bresenham-balanced chunk list: 3 base chunks + possibly 1 tail chunk,
    // tail spread evenly across warps (hence across SMs).
    const int fw    = (w * 17) / 37;
    const int fw1   = ((w + 1) * 17) / 37;
    const int nmine = 3 + (fw1 - fw);

    for (int k = 0; k < nmine; k++) {
        const int chunk = (k < 3) ? (w + k * NWARPS) : (BASE_CHUNKS + fw);
        const int b0 = chunk * S;
        float gate[S];

        // ---- per set: load, features, stage 1 (masked sum of relu(f@W1+b1)) ----
        #pragma unroll
        for (int s = 0; s < S; s++) {
            const int bset = b0 + s;
            int valid = 0;
            if (lane < P) {
                const int idx = bset * P + lane;
                valid = (mask[idx] != 0);
                if (valid) {
                    const float2 a  = ((const float2*)actor_locs)[bset];
                    const float2 pl = ((const float2*)player_locs)[idx];
                    const float2 fl = ((const float2*)flags)[idx];
                    const float dx = pl.x - a.x;
                    const float dy = pl.y - a.y;
                    const float d2 = fmaf(dx, dx, dy * dy);
                    const float dist = (d2 > 0.f) ? d2 * rsqrtf(d2) : 0.f;
                    const float ang  = fast_atan2(dy, dx);
                    sfd[wip][lane][0] = make_float4(dx, dx, dy, dy);
                    sfd[wip][lane][1] = make_float4(dist, dist, ang, ang);
                    sfd[wip][lane][2] = make_float4(fl.x, fl.x, fl.y, fl.y);
                }
            }
            unsigned bal = __ballot_sync(0xffffffffu, valid);  // also orders STS above
            const int cnt = __popc(bal);

            float ha = 0.f, hb = 0.f;
            while (bal) {
                const int p = __ffs(bal) - 1;
                bal &= bal - 1;                       // warp-uniform
                const ulonglong2* f = (const ulonglong2*)&sfd[wip][p][0];
                const ulonglong2 f0 = f[0];           // broadcast LDS.128
                const ulonglong2 f1 = f[1];
                const ulonglong2 f2 = f[2];
                unsigned long long vab = b1ab;
                vab = fma2(f0.x, w1ab[0], vab);
                vab = fma2(f0.y, w1ab[1], vab);
                vab = fma2(f1.x, w1ab[2], vab);
                vab = fma2(f1.y, w1ab[3], vab);
                vab = fma2(f2.x, w1ab[4], vab);
                vab = fma2(f2.y, w1ab[5], vab);
                float va, vb;
                unpack2(vab, va, vb);
                ha += fmaxf(va, 0.f);
                hb += fmaxf(vb, 0.f);
            }

            const float rc = (cnt > 0) ? __fdividef(1.0f, (float)cnt) : 0.0f;
            gate[s] = (cnt > 0) ? 1.0f : 0.0f;
            shh[wip][lane     ][s] = ha * rc;
            shh[wip][lane + 32][s] = hb * rc;
            __syncwarp();   // protect sfd overwrite next set / shh reads in stage 2
        }

        // ---- stage 2: out[s] = h[s] @ W2 + gate[s]*b2, 4 sets at a time ----
        unsigned long long acc01[4], acc23[4];
        #pragma unroll
        for (int c = 0; c < 4; c++) {
            acc01[c] = pack2(bv[c] * gate[0], bv[c] * gate[1]);
            acc23[c] = pack2(bv[c] * gate[2], bv[c] * gate[3]);
        }

        const float4* w2r  = (const float4*)sW2;
        const float4* hrow = (const float4*)&shh[wip][0][0];
        #pragma unroll
        for (int j = 0; j < HID; j++) {
            const float4 wv = w2r[j * (OUTD / 4) + lane];  // per-lane LDS.128
            const float4 hv = hrow[j];                     // broadcast: h_j, 4 sets
            const unsigned long long h01 = pack2(hv.x, hv.y);
            const unsigned long long h23 = pack2(hv.z, hv.w);
            const unsigned long long wd0 = pack2(wv.x, wv.x);
            const unsigned long long wd1 = pack2(wv.y, wv.y);
            const unsigned long long wd2 = pack2(wv.z, wv.z);
            const unsigned long long wd3 = pack2(wv.w, wv.w);
            acc01[0] = fma2(h01, wd0, acc01[0]);  acc23[0] = fma2(h23, wd0, acc23[0]);
            acc01[1] = fma2(h01, wd1, acc01[1]);  acc23[1] = fma2(h23, wd1, acc23[1]);
            acc01[2] = fma2(h01, wd2, acc01[2]);  acc23[2] = fma2(h23, wd2, acc23[2]);
            acc01[3] = fma2(h01, wd3, acc01[3]);  acc23[3] = fma2(h23, wd3, acc23[3]);
        }

        float4 o0, o1, o2, o3;
        unpack2(acc01[0], o0.x, o1.x);  unpack2(acc23[0], o2.x, o3.x);
        unpack2(acc01[1], o0.y, o1.y);  unpack2(acc23[1], o2.y, o3.y);
        unpack2(acc01[2], o0.z, o1.z);  unpack2(acc23[2], o2.z, o3.z);
        unpack2(acc01[3], o0.w, o1.w);  unpack2(acc23[3], o2.w, o3.w);
        float4* ov = (float4*)out;
        ov[(b0 + 0) * (OUTD / 4) + lane] = o0;
        ov[(b0 + 1) * (OUTD / 4) + lane] = o1;
        ov[(b0 + 2) * (OUTD / 4) + lane] = o2;
        ov[(b0 + 3) * (OUTD / 4) + lane] = o3;
    }
}

extern "C" void kernel_launch(void* const* d_in, const int* in_sizes, int n_in,
                              void* d_out, int out_size)
{
    const float* player_locs = (const float*)d_in[0];
    const float* actor_locs  = (const float*)d_in[1];
    const float* flags       = (const float*)d_in[2];
    const int*   mask        = (const int*)  d_in[3];
    const float* W1          = (const float*)d_in[4];
    const float* b1          = (const float*)d_in[5];
    const float* W2          = (const float*)d_in[6];
    const float* b2          = (const float*)d_in[7];
    float*       out         = (float*)d_out;

    set_encoder_kernel<<<GRID, THREADS>>>(player_locs, actor_locs, flags, mask,
                                          W1, b1, W2, b2, out);
}